// round 3
// baseline (speedup 1.0000x reference)
#include <cuda_runtime.h>
#include <cuda_fp16.h>

#define B_  16
#define S_  2048
#define D_  128
#define TM  128         // q rows per CTA
#define TN  64          // k rows per tile
#define KTILES (S_/TN)  // 32
#define THREADS 256
#define CTX_ELEMS (B_*S_*D_)

// scratch for per-row 1/Z between kernels (no allocations allowed)
__device__ float g_invZ[B_*S_];

struct SmemK1 {
    __align__(16) half  K[TN][136];       // 17408 B (272B row stride: conflict-free)
    __align__(16) half  V[TN][136];       // 17408 B
    __align__(16) float stg[2][TN][128];  // fp32 staging: [0]=K,[1]=V, 65536 B
};                                        // total 100352 B (dynamic smem)

__device__ __forceinline__ unsigned smem_u32(const void* p) {
    return (unsigned)__cvta_generic_to_shared(p);
}
__device__ __forceinline__ unsigned packh2(float a, float b) {
    __half2 h = __floats2half2_rn(a, b);
    return *reinterpret_cast<unsigned*>(&h);
}
__device__ __forceinline__ float ex2f(float x) {
    float y;
    asm volatile("ex2.approx.ftz.f32 %0, %1;" : "=f"(y) : "f"(x));
    return y;
}
__device__ __forceinline__ void mma16816(float c[4], const unsigned a[4],
                                         unsigned b0, unsigned b1) {
    asm volatile(
        "mma.sync.aligned.m16n8k16.row.col.f32.f16.f16.f32 "
        "{%0,%1,%2,%3}, {%4,%5,%6,%7}, {%8,%9}, {%0,%1,%2,%3};"
        : "+f"(c[0]), "+f"(c[1]), "+f"(c[2]), "+f"(c[3])
        : "r"(a[0]), "r"(a[1]), "r"(a[2]), "r"(a[3]), "r"(b0), "r"(b1));
}
__device__ __forceinline__ void ldmx4(unsigned& r0, unsigned& r1,
                                      unsigned& r2, unsigned& r3, unsigned a) {
    asm volatile("ldmatrix.sync.aligned.m8n8.x4.shared.b16 {%0,%1,%2,%3}, [%4];"
                 : "=r"(r0), "=r"(r1), "=r"(r2), "=r"(r3) : "r"(a));
}
__device__ __forceinline__ void ldmx4t(unsigned& r0, unsigned& r1,
                                       unsigned& r2, unsigned& r3, unsigned a) {
    asm volatile("ldmatrix.sync.aligned.m8n8.x4.trans.shared.b16 {%0,%1,%2,%3}, [%4];"
                 : "=r"(r0), "=r"(r1), "=r"(r2), "=r"(r3) : "r"(a));
}
__device__ __forceinline__ void cp16(void* sdst, const void* gsrc) {
    asm volatile("cp.async.cg.shared.global [%0], [%1], 16;"
                 :: "r"(smem_u32(sdst)), "l"(gsrc));
}

// Kernel 1: per (batch, 128-row q-tile), 8 warps. cp.async-pipelined over K/V:
//   S = (Q*scale*log2e) @ K^T   (fp16 mma via ldmatrix.x4, fp32 acc)
//   p = ex2(S) -> half2 probs (unnormalized) packed into the low half of each
//       attn row's fp32 slot; rowsum Z in regs; ctx += P @ V (fp16 A-frags
//       reused from the packed probs); ctx normalized by 1/Z at the end.
__global__ void __launch_bounds__(THREADS, 1) attn_k1(
    const float* __restrict__ q, const float* __restrict__ k,
    const float* __restrict__ v, float* __restrict__ out)
{
    extern __shared__ char smem_raw[];
    SmemK1& sm = *reinterpret_cast<SmemK1*>(smem_raw);

    float* ctx   = out;
    half*  attnh = (half*)(out + CTX_ELEMS);   // packed fp16 probs (low half of rows)

    const int b    = blockIdx.y;
    const int qt   = blockIdx.x;
    const int tid  = threadIdx.x;
    const int w    = tid >> 5;
    const int lane = tid & 31;
    const int g    = lane >> 2;
    const int i4   = lane & 3;

    const int r0 = qt * TM + w * 16 + g;
    const int r1 = r0 + 8;

    // ---- Q fragments with scale*log2e folded in ----
    const float SC = 0.08838834764831845f * 1.4426950408889634f;
    unsigned aq[8][4];
    {
        const float* q0 = q + ((size_t)b * S_ + r0) * D_;
        const float* q1 = q + ((size_t)b * S_ + r1) * D_;
        #pragma unroll
        for (int ks = 0; ks < 8; ks++) {
            const int c = ks * 16 + 2 * i4;
            float2 x0 = *(const float2*)(q0 + c);
            float2 x1 = *(const float2*)(q1 + c);
            float2 x2 = *(const float2*)(q0 + c + 8);
            float2 x3 = *(const float2*)(q1 + c + 8);
            aq[ks][0] = packh2(x0.x * SC, x0.y * SC);
            aq[ks][1] = packh2(x1.x * SC, x1.y * SC);
            aq[ks][2] = packh2(x2.x * SC, x2.y * SC);
            aq[ks][3] = packh2(x3.x * SC, x3.y * SC);
        }
    }

    const float* kbase = k + (size_t)b * S_ * D_;
    const float* vbase = v + (size_t)b * S_ * D_;

    // issue cp.async for K/V tile kt into staging
    auto issue_tile = [&](int kt) {
        const float* kg = kbase + (size_t)kt * TN * D_;
        const float* vg = vbase + (size_t)kt * TN * D_;
        #pragma unroll
        for (int it = 0; it < 8; it++) {
            const int idx = it * THREADS + tid;
            const int row = idx >> 5;
            const int c4  = (idx & 31) * 4;
            cp16(&sm.stg[0][row][c4], kg + row * D_ + c4);
            cp16(&sm.stg[1][row][c4], vg + row * D_ + c4);
        }
        asm volatile("cp.async.commit_group;");
    };
    issue_tile(0);

    float acc[16][4];
    #pragma unroll
    for (int nt = 0; nt < 16; nt++)
        #pragma unroll
        for (int j = 0; j < 4; j++) acc[nt][j] = 0.f;
    float zp0 = 0.f, zp1 = 0.f;

    for (int kt = 0; kt < KTILES; kt++) {
        asm volatile("cp.async.wait_group 0;" ::: "memory");
        __syncthreads();   // staging ready for all; fp16 tiles free (prev compute done)

        // ---- convert staged fp32 -> fp16 tiles ----
        #pragma unroll
        for (int it = 0; it < 8; it++) {
            const int idx = it * THREADS + tid;
            const int row = idx >> 5;
            const int c4  = (idx & 31) * 4;
            float4 x = *(const float4*)&sm.stg[0][row][c4];
            uint2 uk;
            uk.x = packh2(x.x, x.y); uk.y = packh2(x.z, x.w);
            *(uint2*)&sm.K[row][c4] = uk;
            float4 y = *(const float4*)&sm.stg[1][row][c4];
            uint2 uv;
            uv.x = packh2(y.x, y.y); uv.y = packh2(y.z, y.w);
            *(uint2*)&sm.V[row][c4] = uv;
        }
        __syncthreads();   // fp16 tiles visible; staging free

        if (kt + 1 < KTILES) issue_tile(kt + 1);   // overlaps with compute below

        // ---- QK: S tile m16 x n64 per warp ----
        float sc[8][4];
        #pragma unroll
        for (int nt = 0; nt < 8; nt++)
            #pragma unroll
            for (int j = 0; j < 4; j++) sc[nt][j] = 0.f;

        const int lm_row = (lane & 7);
        const int lm_m   = lane >> 3;
        #pragma unroll
        for (int ks = 0; ks < 8; ks++) {
            unsigned kb[8][2];
            #pragma unroll
            for (int p = 0; p < 4; p++) {
                const int row = p * 16 + (lm_m >> 1) * 8 + lm_row;
                const int col = ks * 16 + (lm_m & 1) * 8;
                ldmx4(kb[2*p][0], kb[2*p][1], kb[2*p+1][0], kb[2*p+1][1],
                      smem_u32(&sm.K[row][col]));
            }
            #pragma unroll
            for (int nt = 0; nt < 8; nt++)
                mma16816(sc[nt], aq[ks], kb[nt][0], kb[nt][1]);
        }

        // ---- exp + rowsum + pack half2 ----
        unsigned ph0[8], ph1[8];
        #pragma unroll
        for (int nt = 0; nt < 8; nt++) {
            float e0 = ex2f(sc[nt][0]), e1 = ex2f(sc[nt][1]);
            float e2 = ex2f(sc[nt][2]), e3 = ex2f(sc[nt][3]);
            zp0 += e0 + e1;
            zp1 += e2 + e3;
            ph0[nt] = packh2(e0, e1);
            ph1[nt] = packh2(e2, e3);
        }

        // ---- store packed probs (row r occupies halfs [r*4096, r*4096+2048)) ----
        {
            half* a0 = attnh + (size_t)(b * S_ + r0) * 4096 + kt * TN + 2 * i4;
            half* a1 = attnh + (size_t)(b * S_ + r1) * 4096 + kt * TN + 2 * i4;
            #pragma unroll
            for (int nt = 0; nt < 8; nt++) {
                *(unsigned*)(a0 + nt * 8) = ph0[nt];
                *(unsigned*)(a1 + nt * 8) = ph1[nt];
            }
        }

        // ---- PV: ctx += P @ V (half2 probs reused as A-frags) ----
        #pragma unroll
        for (int kk = 0; kk < 4; kk++) {
            unsigned pa[4] = { ph0[2*kk], ph1[2*kk], ph0[2*kk+1], ph1[2*kk+1] };
            #pragma unroll
            for (int ntp = 0; ntp < 8; ntp++) {
                const int row = kk * 16 + (lm_m & 1) * 8 + lm_row;
                const int col = (ntp * 2 + (lane >> 4)) * 8;
                unsigned b0, b1, b2, b3;
                ldmx4t(b0, b1, b2, b3, smem_u32(&sm.V[row][col]));
                mma16816(acc[2*ntp],     pa, b0, b1);
                mma16816(acc[2*ntp + 1], pa, b2, b3);
            }
        }
    }

    // ---- rowsum reduce (4 lanes share a row) ----
    float z0 = zp0;
    z0 += __shfl_xor_sync(0xffffffffu, z0, 1);
    z0 += __shfl_xor_sync(0xffffffffu, z0, 2);
    float z1 = zp1;
    z1 += __shfl_xor_sync(0xffffffffu, z1, 1);
    z1 += __shfl_xor_sync(0xffffffffu, z1, 2);
    const float iz0 = 1.0f / z0;
    const float iz1 = 1.0f / z1;
    if (i4 == 0) {
        g_invZ[b * S_ + r0] = iz0;
        g_invZ[b * S_ + r1] = iz1;
    }

    // ---- normalized context writeback ----
    float* c0p = ctx + ((size_t)b * S_ + r0) * D_ + 2 * i4;
    float* c1p = ctx + ((size_t)b * S_ + r1) * D_ + 2 * i4;
    #pragma unroll
    for (int nt = 0; nt < 16; nt++) {
        *(float2*)(c0p + nt * 8) = make_float2(acc[nt][0] * iz0, acc[nt][1] * iz0);
        *(float2*)(c1p + nt * 8) = make_float2(acc[nt][2] * iz1, acc[nt][3] * iz1);
    }
}

// Kernel 2: in-place expand packed half2 probs -> normalized fp32.
// One block per attn row: all reads (low 4KB) complete before any writes (8KB).
__global__ void __launch_bounds__(256) attn_k2(float* __restrict__ out)
{
    const half* attnh = (const half*)(out + CTX_ELEMS);
    float*      attn  = out + CTX_ELEMS;
    const int row = blockIdx.x;
    const int t   = threadIdx.x;
    const float iz = g_invZ[row];

    float4 raw = ((const float4*)(attnh + (size_t)row * 4096))[t];  // 8 halfs
    const __half2* hp = (const __half2*)&raw;
    float2 f0 = __half22float2(hp[0]);
    float2 f1 = __half22float2(hp[1]);
    float2 f2 = __half22float2(hp[2]);
    float2 f3 = __half22float2(hp[3]);
    __syncthreads();   // all reads done before any fp32 writes to this row

    float4* dst = (float4*)(attn + (size_t)row * S_) + t * 2;
    dst[0] = make_float4(f0.x * iz, f0.y * iz, f1.x * iz, f1.y * iz);
    dst[1] = make_float4(f2.x * iz, f2.y * iz, f3.x * iz, f3.y * iz);
}

extern "C" void kernel_launch(void* const* d_in, const int* in_sizes, int n_in,
                              void* d_out, int out_size)
{
    const float* q = (const float*)d_in[0];
    const float* k = (const float*)d_in[1];
    const float* v = (const float*)d_in[2];
    float* out = (float*)d_out;

    static bool attr_set = false;
    if (!attr_set) {
        cudaFuncSetAttribute(attn_k1, cudaFuncAttributeMaxDynamicSharedMemorySize,
                             (int)sizeof(SmemK1));
        attr_set = true;
    }

    dim3 g1(S_ / TM, B_);
    attn_k1<<<g1, THREADS, sizeof(SmemK1)>>>(q, k, v, out);
    attn_k2<<<B_ * S_, 256>>>(out);
}

// round 4
// speedup vs baseline: 1.0226x; 1.0226x over previous
#include <cuda_runtime.h>
#include <cuda_fp16.h>

#define B_  16
#define S_  2048
#define D_  128
#define TM  128         // q rows per CTA
#define TN  64          // k rows per tile
#define KTILES (S_/TN)  // 32
#define THREADS 256
#define CTX_ELEMS (B_*S_*D_)

// scratch for per-row 1/Z between kernels (no allocations allowed)
__device__ float g_invZ[B_*S_];

__device__ __forceinline__ unsigned smem_u32(const void* p) {
    return (unsigned)__cvta_generic_to_shared(p);
}
__device__ __forceinline__ unsigned packh2(float a, float b) {
    __half2 h = __floats2half2_rn(a, b);
    return *reinterpret_cast<unsigned*>(&h);
}
__device__ __forceinline__ float ex2f(float x) {
    float y;
    asm volatile("ex2.approx.ftz.f32 %0, %1;" : "=f"(y) : "f"(x));
    return y;
}
__device__ __forceinline__ void mma16816(float c[4], const unsigned a[4],
                                         unsigned b0, unsigned b1) {
    asm volatile(
        "mma.sync.aligned.m16n8k16.row.col.f32.f16.f16.f32 "
        "{%0,%1,%2,%3}, {%4,%5,%6,%7}, {%8,%9}, {%0,%1,%2,%3};"
        : "+f"(c[0]), "+f"(c[1]), "+f"(c[2]), "+f"(c[3])
        : "r"(a[0]), "r"(a[1]), "r"(a[2]), "r"(a[3]), "r"(b0), "r"(b1));
}
__device__ __forceinline__ void ldmx4(unsigned& r0, unsigned& r1,
                                      unsigned& r2, unsigned& r3, unsigned a) {
    asm volatile("ldmatrix.sync.aligned.m8n8.x4.shared.b16 {%0,%1,%2,%3}, [%4];"
                 : "=r"(r0), "=r"(r1), "=r"(r2), "=r"(r3) : "r"(a));
}
__device__ __forceinline__ void ldmx4t(unsigned& r0, unsigned& r1,
                                       unsigned& r2, unsigned& r3, unsigned a) {
    asm volatile("ldmatrix.sync.aligned.m8n8.x4.trans.shared.b16 {%0,%1,%2,%3}, [%4];"
                 : "=r"(r0), "=r"(r1), "=r"(r2), "=r"(r3) : "r"(a));
}

// Kernel 1: per (batch, 128-row q-tile), 8 warps. Register-prefetch pipeline:
// K/V tile t+1 is LDG'd into registers during tile t's MMA phase; at tile top
// the registers are converted+stored to fp16 smem directly (no fp32 staging).
__global__ void __launch_bounds__(THREADS, 1) attn_k1(
    const float* __restrict__ q, const float* __restrict__ k,
    const float* __restrict__ v, float* __restrict__ out)
{
    // 136-half row stride (272B = 17*16B): conflict-free & 16B aligned
    __shared__ __align__(16) half Ks[TN][136];
    __shared__ __align__(16) half Vs[TN][136];

    float* ctx   = out;
    half*  attnh = (half*)(out + CTX_ELEMS);   // packed fp16 probs (low half of rows)

    const int b    = blockIdx.y;
    const int qt   = blockIdx.x;
    const int tid  = threadIdx.x;
    const int w    = tid >> 5;
    const int lane = tid & 31;
    const int g    = lane >> 2;
    const int i4   = lane & 3;

    const int r0 = qt * TM + w * 16 + g;
    const int r1 = r0 + 8;

    // ---- Q fragments with scale*log2e folded in ----
    const float SC = 0.08838834764831845f * 1.4426950408889634f;
    unsigned aq[8][4];
    {
        const float* q0 = q + ((size_t)b * S_ + r0) * D_;
        const float* q1 = q + ((size_t)b * S_ + r1) * D_;
        #pragma unroll
        for (int ks = 0; ks < 8; ks++) {
            const int c = ks * 16 + 2 * i4;
            float2 x0 = *(const float2*)(q0 + c);
            float2 x1 = *(const float2*)(q1 + c);
            float2 x2 = *(const float2*)(q0 + c + 8);
            float2 x3 = *(const float2*)(q1 + c + 8);
            aq[ks][0] = packh2(x0.x * SC, x0.y * SC);
            aq[ks][1] = packh2(x1.x * SC, x1.y * SC);
            aq[ks][2] = packh2(x2.x * SC, x2.y * SC);
            aq[ks][3] = packh2(x3.x * SC, x3.y * SC);
        }
    }

    const float* kbase = k + (size_t)b * S_ * D_;
    const float* vbase = v + (size_t)b * S_ * D_;

    // this thread's 8 float4 slots within a tile
    int prow[8], pc4[8];
    #pragma unroll
    for (int it = 0; it < 8; it++) {
        const int idx = it * THREADS + tid;
        prow[it] = idx >> 5;
        pc4[it]  = (idx & 31) * 4;
    }

    float4 kr[8], vr[8];
    #pragma unroll
    for (int it = 0; it < 8; it++) {
        kr[it] = *(const float4*)(kbase + (size_t)prow[it] * D_ + pc4[it]);
        vr[it] = *(const float4*)(vbase + (size_t)prow[it] * D_ + pc4[it]);
    }

    float acc[16][4];
    #pragma unroll
    for (int nt = 0; nt < 16; nt++)
        #pragma unroll
        for (int j = 0; j < 4; j++) acc[nt][j] = 0.f;
    float zp0 = 0.f, zp1 = 0.f;

    for (int kt = 0; kt < KTILES; kt++) {
        __syncthreads();   // prev tile consumed; smem free
        // ---- registers -> fp16 smem tiles ----
        #pragma unroll
        for (int it = 0; it < 8; it++) {
            uint2 uk, uv;
            uk.x = packh2(kr[it].x, kr[it].y); uk.y = packh2(kr[it].z, kr[it].w);
            uv.x = packh2(vr[it].x, vr[it].y); uv.y = packh2(vr[it].z, vr[it].w);
            *(uint2*)&Ks[prow[it]][pc4[it]] = uk;
            *(uint2*)&Vs[prow[it]][pc4[it]] = uv;
        }
        __syncthreads();   // fp16 tiles visible

        // ---- prefetch next tile into registers (latency hidden by MMA) ----
        if (kt + 1 < KTILES) {
            const float* kg = kbase + (size_t)(kt + 1) * TN * D_;
            const float* vg = vbase + (size_t)(kt + 1) * TN * D_;
            #pragma unroll
            for (int it = 0; it < 8; it++) {
                kr[it] = *(const float4*)(kg + (size_t)prow[it] * D_ + pc4[it]);
                vr[it] = *(const float4*)(vg + (size_t)prow[it] * D_ + pc4[it]);
            }
        }

        // ---- QK: S tile m16 x n64 per warp ----
        float sc[8][4];
        #pragma unroll
        for (int nt = 0; nt < 8; nt++)
            #pragma unroll
            for (int j = 0; j < 4; j++) sc[nt][j] = 0.f;

        const int lm_row = (lane & 7);
        const int lm_m   = lane >> 3;
        #pragma unroll
        for (int ks = 0; ks < 8; ks++) {
            unsigned kb[8][2];
            #pragma unroll
            for (int p = 0; p < 4; p++) {
                const int row = p * 16 + (lm_m >> 1) * 8 + lm_row;
                const int col = ks * 16 + (lm_m & 1) * 8;
                ldmx4(kb[2*p][0], kb[2*p][1], kb[2*p+1][0], kb[2*p+1][1],
                      smem_u32(&Ks[row][col]));
            }
            #pragma unroll
            for (int nt = 0; nt < 8; nt++)
                mma16816(sc[nt], aq[ks], kb[nt][0], kb[nt][1]);
        }

        // ---- exp + rowsum + pack half2 ----
        unsigned ph0[8], ph1[8];
        #pragma unroll
        for (int nt = 0; nt < 8; nt++) {
            float e0 = ex2f(sc[nt][0]), e1 = ex2f(sc[nt][1]);
            float e2 = ex2f(sc[nt][2]), e3 = ex2f(sc[nt][3]);
            zp0 += e0 + e1;
            zp1 += e2 + e3;
            ph0[nt] = packh2(e0, e1);
            ph1[nt] = packh2(e2, e3);
        }

        // ---- store packed probs (row r occupies halfs [r*4096, r*4096+2048)) ----
        {
            half* a0 = attnh + (size_t)(b * S_ + r0) * 4096 + kt * TN + 2 * i4;
            half* a1 = attnh + (size_t)(b * S_ + r1) * 4096 + kt * TN + 2 * i4;
            #pragma unroll
            for (int nt = 0; nt < 8; nt++) {
                *(unsigned*)(a0 + nt * 8) = ph0[nt];
                *(unsigned*)(a1 + nt * 8) = ph1[nt];
            }
        }

        // ---- PV: ctx += P @ V (half2 probs reused as A-frags) ----
        #pragma unroll
        for (int kk = 0; kk < 4; kk++) {
            unsigned pa[4] = { ph0[2*kk], ph1[2*kk], ph0[2*kk+1], ph1[2*kk+1] };
            #pragma unroll
            for (int ntp = 0; ntp < 8; ntp++) {
                const int row = kk * 16 + (lm_m & 1) * 8 + lm_row;
                const int col = (ntp * 2 + (lane >> 4)) * 8;
                unsigned b0, b1, b2, b3;
                ldmx4t(b0, b1, b2, b3, smem_u32(&Vs[row][col]));
                mma16816(acc[2*ntp],     pa, b0, b1);
                mma16816(acc[2*ntp + 1], pa, b2, b3);
            }
        }
    }

    // ---- rowsum reduce (4 lanes share a row) ----
    float z0 = zp0;
    z0 += __shfl_xor_sync(0xffffffffu, z0, 1);
    z0 += __shfl_xor_sync(0xffffffffu, z0, 2);
    float z1 = zp1;
    z1 += __shfl_xor_sync(0xffffffffu, z1, 1);
    z1 += __shfl_xor_sync(0xffffffffu, z1, 2);
    const float iz0 = 1.0f / z0;
    const float iz1 = 1.0f / z1;
    if (i4 == 0) {
        g_invZ[b * S_ + r0] = iz0;
        g_invZ[b * S_ + r1] = iz1;
    }

    // ---- normalized context writeback ----
    float* c0p = ctx + ((size_t)b * S_ + r0) * D_ + 2 * i4;
    float* c1p = ctx + ((size_t)b * S_ + r1) * D_ + 2 * i4;
    #pragma unroll
    for (int nt = 0; nt < 16; nt++) {
        *(float2*)(c0p + nt * 8) = make_float2(acc[nt][0] * iz0, acc[nt][1] * iz0);
        *(float2*)(c1p + nt * 8) = make_float2(acc[nt][2] * iz1, acc[nt][3] * iz1);
    }
}

// Kernel 2: in-place expand packed half2 probs -> normalized fp32.
// 4 rows per 256-thread block (64 threads/row), 4 independent reads per
// thread (MLP=4) before the barrier, then 8 coalesced float4 writes.
__global__ void __launch_bounds__(256) attn_k2(float* __restrict__ out)
{
    const half* attnh = (const half*)(out + CTX_ELEMS);
    float*      attn  = out + CTX_ELEMS;
    const int row = blockIdx.x * 4 + (threadIdx.x >> 6);
    const int t   = threadIdx.x & 63;
    const float iz = g_invZ[row];

    const float4* src = (const float4*)(attnh + (size_t)row * 4096);
    float4 raw[4];
    #pragma unroll
    for (int j = 0; j < 4; j++) raw[j] = src[t + j * 64];   // 4 independent LDG.128
    __syncthreads();   // all reads in block done before any fp32 writes

    float4* dst = (float4*)(attn + (size_t)row * S_);
    #pragma unroll
    for (int j = 0; j < 4; j++) {
        const __half2* hp = (const __half2*)&raw[j];
        float2 f0 = __half22float2(hp[0]);
        float2 f1 = __half22float2(hp[1]);
        float2 f2 = __half22float2(hp[2]);
        float2 f3 = __half22float2(hp[3]);
        dst[2 * (t + j * 64)]     = make_float4(f0.x * iz, f0.y * iz, f1.x * iz, f1.y * iz);
        dst[2 * (t + j * 64) + 1] = make_float4(f2.x * iz, f2.y * iz, f3.x * iz, f3.y * iz);
    }
}

extern "C" void kernel_launch(void* const* d_in, const int* in_sizes, int n_in,
                              void* d_out, int out_size)
{
    const float* q = (const float*)d_in[0];
    const float* k = (const float*)d_in[1];
    const float* v = (const float*)d_in[2];
    float* out = (float*)d_out;

    dim3 g1(S_ / TM, B_);
    attn_k1<<<g1, THREADS>>>(q, k, v, out);
    attn_k2<<<(B_ * S_) / 4, 256>>>(out);
}